// round 16
// baseline (speedup 1.0000x reference)
#include <cuda_runtime.h>
#include <cuda_fp16.h>
#include <cstdint>

#define NB 64
#define NT 256
#define NC 384
#define NH 6
#define ND 64
#define BTOK (NB*NT)                 // 16384 tokens
#define BHTD ((size_t)NB*NH*NT*ND)   // 6,291,456 elements per q/k/v
#define NQKV 1152                    // 3*384 output cols of merged qkv

// ---------------- scratch (no allocations allowed) ----------------
__device__ __half g_qkvh[3 * BHTD];                // q(pre-scaled),k,v [z][B,H,T,D]
__device__ __half g_aoh[(size_t)BTOK * NC];        // attn out [B,T,H*D]
__device__ __half g_xh[(size_t)BTOK * NC];         // x in fp16 [M][K]
__device__ __half g_wth[(size_t)NQKV * NC];        // qkv weights [n][k] K-major
__device__ __half g_wpth[(size_t)NC * NC];         // Wp transposed [n][k]

// ---------------- helpers ----------------
__device__ __forceinline__ void mma16(float d[4], const uint32_t a[4], const uint32_t b[2]) {
    asm volatile(
        "mma.sync.aligned.m16n8k16.row.col.f32.f16.f16.f32 "
        "{%0,%1,%2,%3}, {%4,%5,%6,%7}, {%8,%9}, {%0,%1,%2,%3};"
        : "+f"(d[0]), "+f"(d[1]), "+f"(d[2]), "+f"(d[3])
        : "r"(a[0]), "r"(a[1]), "r"(a[2]), "r"(a[3]), "r"(b[0]), "r"(b[1]));
}

__device__ __forceinline__ void ldsm_x4(uint32_t r[4], uint32_t addr) {
    asm volatile("ldmatrix.sync.aligned.m8n8.x4.shared.b16 {%0,%1,%2,%3}, [%4];"
        : "=r"(r[0]), "=r"(r[1]), "=r"(r[2]), "=r"(r[3]) : "r"(addr));
}

__device__ __forceinline__ uint32_t packh2(float lo, float hi) {
    __half2 h = __floats2half2_rn(lo, hi);
    return *reinterpret_cast<uint32_t*>(&h);
}

__device__ __forceinline__ void cpa16(uint32_t dst, const void* src) {
    asm volatile("cp.async.cg.shared.global [%0], [%1], 16;" :: "r"(dst), "l"(src));
}
__device__ __forceinline__ void cpa_commit() { asm volatile("cp.async.commit_group;"); }
__device__ __forceinline__ void cpa_wait1()  { asm volatile("cp.async.wait_group 1;"); }
__device__ __forceinline__ void cpa_wait0()  { asm volatile("cp.async.wait_group 0;"); }

// ---------------------------------------------------------------------------
// Kernel 0: prep — x -> half; weights transposed -> half [n][k].
// ---------------------------------------------------------------------------
#define XB 3072                       // 16384*384/8/256
#define WQKV (NQKV * NC)              // 442368
#define WBLK ((WQKV + NC * NC + 255) / 256)   // 2304
__global__ __launch_bounds__(256) void prep(
    const float* __restrict__ x,
    const float* __restrict__ Wq, const float* __restrict__ Wk,
    const float* __restrict__ Wv, const float* __restrict__ Wp)
{
    int bid = blockIdx.x;
    if (bid < XB) {
        size_t i = ((size_t)bid * 256 + threadIdx.x) * 8;
        float4 v0 = *(const float4*)(x + i);
        float4 v1 = *(const float4*)(x + i + 4);
        uint4 p;
        p.x = packh2(v0.x, v0.y); p.y = packh2(v0.z, v0.w);
        p.z = packh2(v1.x, v1.y); p.w = packh2(v1.z, v1.w);
        *(uint4*)(g_xh + i) = p;
    } else {
        int e = (bid - XB) * 256 + threadIdx.x;
        if (e < WQKV) {
            int n = e / NC, k = e % NC;
            int z = n / NC, rn = n % NC, hh = rn >> 6, d = rn & 63;
            const float* W = (z == 0 ? Wq : (z == 1 ? Wk : Wv));
            g_wth[e] = __float2half_rn(W[(hh * NC + k) * ND + d]);
        } else {
            int e2 = e - WQKV;
            int n = e2 / NC, k = e2 % NC;
            g_wpth[e2] = __float2half_rn(Wp[k * NC + n]);
        }
    }
}

// ---------------------------------------------------------------------------
// fp16 pipelined GEMM core: CTA 128x128, 8 warps (2x4), warp tile 64x32,
// k-chunk 64, 3-stage cp.async. Pitch 36 words = 144 B rows.
// ---------------------------------------------------------------------------
#define GP 36                         // words per row (32 used = k-chunk 64)
#define ASW (128 * GP)                // 4608 words
#define STGW (2 * ASW)                // 9216 words per stage (A + B)
#define GEMM_SMEM (3 * STGW * 4)      // 110,592 B
#define KITERS 6                      // 384 / 64

__device__ __forceinline__ void gm_issue(
    uint32_t sbase, const __half* __restrict__ A, const __half* __restrict__ B,
    int m0, int n0, int k0w, int tid)
{
    uint32_t as = sbase, bs = sbase + ASW * 4;
#pragma unroll
    for (int i = 0; i < 4; i++) {
        int e = tid + i * 256;                 // 0..1023
        int r = e >> 3, q = (e & 7) * 4;       // r: row, q: word-in-row
        cpa16(as + (r * GP + q) * 4, (const char*)(A + (size_t)(m0 + r) * NC) + (k0w + q) * 4);
    }
#pragma unroll
    for (int i = 0; i < 4; i++) {
        int e = tid + i * 256;
        int r = e >> 3, q = (e & 7) * 4;
        cpa16(bs + (r * GP + q) * 4, (const char*)(B + (size_t)(n0 + r) * NC) + (k0w + q) * 4);
    }
}

// one k64 step (4 k16 sub-steps); warp tile 64x32; fragments via ldmatrix
__device__ __forceinline__ void gm_step(
    uint32_t asb, uint32_t bsb, int wm, int wn, int lane, float acc[4][4][4])
{
    const int arow = wm + (lane & 15);                    // + mt*16
    const int acol = (lane >> 4) * 4;                     // 0 | 4
    const int brow = wn + (lane & 7) + ((lane & 16) >> 1);// + nt2*16
    const int bcol = (lane & 8) >> 1;                     // 0 | 4
#pragma unroll
    for (int ks = 0; ks < 4; ks++) {
        const int kb = ks * 8;
        uint32_t af[4][4], bf[4][2];
#pragma unroll
        for (int mt = 0; mt < 4; mt++)
            ldsm_x4(af[mt], asb + (((arow + mt * 16) * GP) + kb + acol) * 4);
#pragma unroll
        for (int nt2 = 0; nt2 < 2; nt2++) {
            uint32_t t[4];
            ldsm_x4(t, bsb + (((brow + nt2 * 16) * GP) + kb + bcol) * 4);
            bf[2 * nt2][0] = t[0]; bf[2 * nt2][1] = t[1];
            bf[2 * nt2 + 1][0] = t[2]; bf[2 * nt2 + 1][1] = t[3];
        }
#pragma unroll
        for (int mt = 0; mt < 4; mt++)
#pragma unroll
            for (int nt = 0; nt < 4; nt++)
                mma16(acc[mt][nt], af[mt], bf[nt]);
    }
}

// ---------------------------------------------------------------------------
// Kernel 1: merged QKV GEMM (batch-chunk via mbase). 256 threads / 8 warps.
// ---------------------------------------------------------------------------
__global__ __launch_bounds__(256, 2) void qkv_gemm(int mbase)
{
    extern __shared__ uint32_t sh[];
    const int tid = threadIdx.x, lane = tid & 31, warp = tid >> 5;
    const int gid = lane >> 2, tig = lane & 3;
    const int m0 = mbase + blockIdx.x * 128;
    const int n0 = blockIdx.y * 128;
    const int z = n0 / NC, nb = n0 % NC;
    const int wm = (warp >> 2) * 64, wn = (warp & 3) * 32;
    const uint32_t sb = (uint32_t)__cvta_generic_to_shared(sh);

    float acc[4][4][4];
#pragma unroll
    for (int mt = 0; mt < 4; mt++)
#pragma unroll
        for (int nt = 0; nt < 4; nt++)
#pragma unroll
            for (int q = 0; q < 4; q++) acc[mt][nt][q] = 0.f;

    gm_issue(sb, g_xh, g_wth, m0, n0, 0, tid);  cpa_commit();
    gm_issue(sb + STGW * 4, g_xh, g_wth, m0, n0, 32, tid);  cpa_commit();

    for (int it = 0; it < KITERS; it++) {
        cpa_wait1();
        __syncthreads();
        if (it + 2 < KITERS)
            gm_issue(sb + ((it + 2) % 3) * STGW * 4, g_xh, g_wth, m0, n0, (it + 2) * 32, tid);
        cpa_commit();
        uint32_t buf = sb + (it % 3) * STGW * 4;
        gm_step(buf, buf + ASW * 4, wm, wn, lane, acc);
    }

    const float scale = (z == 0) ? 0.125f : 1.0f;
#pragma unroll
    for (int mt = 0; mt < 4; mt++) {
        int m = m0 + wm + mt * 16 + gid;
        int b1 = m >> 8, t1 = m & 255;
        int b2 = (m + 8) >> 8, t2 = (m + 8) & 255;
#pragma unroll
        for (int nt = 0; nt < 4; nt++) {
            int c = wn + nt * 8 + 2 * tig;
            int nl = nb + c, h = nl >> 6, d = nl & 63;
            __half* p0 = g_qkvh + z * BHTD + (((size_t)b1 * NH + h) * NT + t1) * ND + d;
            __half* p1 = g_qkvh + z * BHTD + (((size_t)b2 * NH + h) * NT + t2) * ND + d;
            *(uint32_t*)p0 = packh2(acc[mt][nt][0] * scale, acc[mt][nt][1] * scale);
            *(uint32_t*)p1 = packh2(acc[mt][nt][2] * scale, acc[mt][nt][3] * scale);
        }
    }
}

// ---------------------------------------------------------------------------
// Kernel 2: causal flash attention per (b,h), batch-chunk via bbase.
// 256 threads. Balanced warp pairing (5 tiles/warp).
// ---------------------------------------------------------------------------
#define KSW 36    // Ks pitch (words): 144 B rows, conflict-free ldsm
#define VSW 132   // Vs pitch (words): 528 B rows, 16B-aligned
#define ATTN_SMEM ((256 * KSW + 64 * VSW) * 4)   // 70,656 B

__global__ __launch_bounds__(256, 2) void attn_kernel(int bbase)
{
    extern __shared__ uint32_t sh[];
    uint32_t* Ks = sh;                  // [s=256][d-pair, 32 used]
    uint32_t* Vs = sh + 256 * KSW;      // [d=64][s-pair, 128 used]

    const int tid = threadIdx.x, lane = tid & 31, warp = tid >> 5;
    const int gid = lane >> 2, tig = lane & 3;
    const int h = blockIdx.x, b = bbase + blockIdx.y;

    const __half* qbh = g_qkvh + ((size_t)(b * NH + h) * NT) * ND;
    const __half* kbh = qbh + BHTD;
    const __half* vbh = qbh + 2 * BHTD;

    uint32_t ksb = (uint32_t)__cvta_generic_to_shared(Ks);
    uint32_t vsb = (uint32_t)__cvta_generic_to_shared(Vs);
#pragma unroll
    for (int i = 0; i < 8; i++) {
        int e = tid + i * 256;
        int s = e >> 3, q = (e & 7) * 4;
        cpa16(ksb + (s * KSW + q) * 4, (const char*)(kbh + (size_t)s * ND) + q * 4);
    }
    cpa_commit();

    // V transpose to [d][s-pair]; banks (4d+sp) mod 32 all distinct
#pragma unroll
    for (int i = 0; i < 32; i++) {
        int e = tid + i * 256;
        int d  = ((e >> 5) & 7) * 8 + (e & 7);
        int sp = (e >> 8) * 4 + ((e >> 3) & 3);
        uint32_t lo = __half_as_ushort(vbh[(size_t)(2 * sp) * ND + d]);
        uint32_t hi = __half_as_ushort(vbh[(size_t)(2 * sp + 1) * ND + d]);
        Vs[d * VSW + sp] = lo | (hi << 16);
    }
    cpa_wait0();
    __syncthreads();

    const uint32_t* qw = (const uint32_t*)qbh;   // [t][32 words]
    const int lrow = (lane & 7) + ((lane & 16) >> 1);
    const int lcol = (lane & 8) >> 1;

    for (int pass = 0; pass < 2; pass++) {
        const int grp = (pass == 0) ? warp : (15 - warp);   // 16-row group, 0..15
        const int qr0 = grp * 16 + gid;                     // global q row
        uint32_t qf[4][4];
#pragma unroll
        for (int kk = 0; kk < 4; kk++) {
            qf[kk][0] = qw[qr0 * 32 + kk * 8 + tig];
            qf[kk][1] = qw[(qr0 + 8) * 32 + kk * 8 + tig];
            qf[kk][2] = qw[qr0 * 32 + kk * 8 + tig + 4];
            qf[kk][3] = qw[(qr0 + 8) * 32 + kk * 8 + tig + 4];
        }

        float oacc[8][4];
#pragma unroll
        for (int nt = 0; nt < 8; nt++)
#pragma unroll
            for (int q = 0; q < 4; q++) oacc[nt][q] = 0.f;
        float l0 = 0.f, l1 = 0.f;

        const int jmax = (grp * 16 + 15) >> 6;
        for (int j = 0; j <= jmax; j++) {
            float sacc[8][4];
#pragma unroll
            for (int nt = 0; nt < 8; nt++)
#pragma unroll
                for (int q = 0; q < 4; q++) sacc[nt][q] = 0.f;

#pragma unroll
            for (int kk = 0; kk < 4; kk++)
#pragma unroll
                for (int nt2 = 0; nt2 < 4; nt2++) {
                    uint32_t t[4];
                    int srow = j * 64 + nt2 * 16 + lrow;
                    ldsm_x4(t, ksb + ((srow * KSW) + kk * 8 + lcol) * 4);
                    mma16(sacc[2 * nt2], qf[kk], t);
                    mma16(sacc[2 * nt2 + 1], qf[kk], t + 2);
                }

            // causal mask (only when this key tile can overlap the diagonal)
            const int qg0 = qr0, qg1 = qr0 + 8;
            if (j * 64 + 63 > grp * 16) {
#pragma unroll
                for (int nt = 0; nt < 8; nt++) {
                    int kg = j * 64 + nt * 8 + 2 * tig;
                    if (kg > qg0) sacc[nt][0] = -1e30f;
                    if (kg + 1 > qg0) sacc[nt][1] = -1e30f;
                    if (kg > qg1) sacc[nt][2] = -1e30f;
                    if (kg + 1 > qg1) sacc[nt][3] = -1e30f;
                }
            }

            // direct softmax: exp + row-sum
            float rs0 = 0.f, rs1 = 0.f;
#pragma unroll
            for (int nt = 0; nt < 8; nt++) {
                sacc[nt][0] = __expf(fminf(sacc[nt][0], 25.f));
                sacc[nt][1] = __expf(fminf(sacc[nt][1], 25.f));
                sacc[nt][2] = __expf(fminf(sacc[nt][2], 25.f));
                sacc[nt][3] = __expf(fminf(sacc[nt][3], 25.f));
                rs0 += sacc[nt][0] + sacc[nt][1];
                rs1 += sacc[nt][2] + sacc[nt][3];
            }
            rs0 += __shfl_xor_sync(0xffffffffu, rs0, 1);
            rs0 += __shfl_xor_sync(0xffffffffu, rs0, 2);
            rs1 += __shfl_xor_sync(0xffffffffu, rs1, 1);
            rs1 += __shfl_xor_sync(0xffffffffu, rs1, 2);
            l0 += rs0;
            l1 += rs1;

            // P -> fp16 A-fragments in registers
            uint32_t pp[4][4];
#pragma unroll
            for (int kw = 0; kw < 4; kw++) {
                pp[kw][0] = packh2(sacc[2 * kw][0],     sacc[2 * kw][1]);
                pp[kw][1] = packh2(sacc[2 * kw][2],     sacc[2 * kw][3]);
                pp[kw][2] = packh2(sacc[2 * kw + 1][0], sacc[2 * kw + 1][1]);
                pp[kw][3] = packh2(sacc[2 * kw + 1][2], sacc[2 * kw + 1][3]);
            }

            // O += P * V
#pragma unroll
            for (int kw = 0; kw < 4; kw++)
#pragma unroll
                for (int dt2 = 0; dt2 < 4; dt2++) {
                    uint32_t t[4];
                    int drow = dt2 * 16 + lrow;
                    ldsm_x4(t, vsb + ((drow * VSW) + j * 32 + kw * 8 + lcol) * 4);
                    mma16(oacc[2 * dt2], pp[kw], t);
                    mma16(oacc[2 * dt2 + 1], pp[kw], t + 2);
                }
        }

        // epilogue -> g_aoh [B,T,H*D] half (rows grp*16 .. grp*16+15)
        const float inv0 = 1.f / l0, inv1 = 1.f / l1;
        __half* op = g_aoh + ((size_t)(b * NT) + grp * 16) * NC + h * ND;
        const int r0 = gid;
#pragma unroll
        for (int nt = 0; nt < 8; nt++) {
            int cc = nt * 8 + 2 * tig;
            *(uint32_t*)(op + (size_t)r0 * NC + cc) =
                packh2(oacc[nt][0] * inv0, oacc[nt][1] * inv0);
            *(uint32_t*)(op + (size_t)(r0 + 8) * NC + cc) =
                packh2(oacc[nt][2] * inv1, oacc[nt][3] * inv1);
        }
    }
}

// ---------------------------------------------------------------------------
// Kernel 3: output projection + bias (batch-chunk via mbase). 256 threads.
// ---------------------------------------------------------------------------
__global__ __launch_bounds__(256, 2) void proj_gemm(
    int mbase, const float* __restrict__ bp, float* __restrict__ out)
{
    extern __shared__ uint32_t sh[];
    const int tid = threadIdx.x, lane = tid & 31, warp = tid >> 5;
    const int gid = lane >> 2, tig = lane & 3;
    const int m0 = mbase + blockIdx.x * 128;
    const int n0 = blockIdx.y * 128;
    const int wm = (warp >> 2) * 64, wn = (warp & 3) * 32;
    const uint32_t sb = (uint32_t)__cvta_generic_to_shared(sh);

    float acc[4][4][4];
#pragma unroll
    for (int mt = 0; mt < 4; mt++)
#pragma unroll
        for (int nt = 0; nt < 4; nt++)
#pragma unroll
            for (int q = 0; q < 4; q++) acc[mt][nt][q] = 0.f;

    gm_issue(sb, g_aoh, g_wpth, m0, n0, 0, tid);  cpa_commit();
    gm_issue(sb + STGW * 4, g_aoh, g_wpth, m0, n0, 32, tid);  cpa_commit();

    for (int it = 0; it < KITERS; it++) {
        cpa_wait1();
        __syncthreads();
        if (it + 2 < KITERS)
            gm_issue(sb + ((it + 2) % 3) * STGW * 4, g_aoh, g_wpth, m0, n0, (it + 2) * 32, tid);
        cpa_commit();
        uint32_t buf = sb + (it % 3) * STGW * 4;
        gm_step(buf, buf + ASW * 4, wm, wn, lane, acc);
    }

#pragma unroll
    for (int mt = 0; mt < 4; mt++) {
        int r = wm + mt * 16 + gid;
#pragma unroll
        for (int nt = 0; nt < 4; nt++) {
            int c = n0 + wn + nt * 8 + 2 * tig;
            float b0 = bp[c], b1 = bp[c + 1];
            *(float2*)(out + (size_t)(m0 + r) * NC + c) =
                make_float2(acc[mt][nt][0] + b0, acc[mt][nt][1] + b1);
            *(float2*)(out + (size_t)(m0 + r + 8) * NC + c) =
                make_float2(acc[mt][nt][2] + b0, acc[mt][nt][3] + b1);
        }
    }
}

// ---------------------------------------------------------------------------
// Launch: 3-chain pipeline — origin stream runs chain 0 (batches 0..20)
// after prep; 2 worker streams (R14-proven count) run chains for batches
// 21..42 and 43..63. Streams/events created once on the first call so the
// capture/teardown memory baseline stays clean.
// ---------------------------------------------------------------------------
extern "C" void kernel_launch(void* const* d_in, const int* in_sizes, int n_in,
                              void* d_out, int out_size)
{
    const float* x  = (const float*)d_in[0];
    const float* Wq = (const float*)d_in[1];
    const float* Wk = (const float*)d_in[2];
    const float* Wv = (const float*)d_in[3];
    const float* Wp = (const float*)d_in[4];
    const float* bp = (const float*)d_in[5];
    float* out = (float*)d_out;

    static cudaStream_t sA = nullptr, sB = nullptr;
    static cudaEvent_t evPrep = nullptr, evA = nullptr, evB = nullptr;
    if (sA == nullptr) {
        int prioLo = 0, prioHi = 0;
        cudaDeviceGetStreamPriorityRange(&prioLo, &prioHi);
        cudaStreamCreateWithPriority(&sA, cudaStreamNonBlocking, prioHi);
        cudaStreamCreateWithPriority(&sB, cudaStreamNonBlocking, prioLo);
        cudaEventCreateWithFlags(&evPrep, cudaEventDisableTiming);
        cudaEventCreateWithFlags(&evA, cudaEventDisableTiming);
        cudaEventCreateWithFlags(&evB, cudaEventDisableTiming);

        cudaFuncSetAttribute(qkv_gemm, cudaFuncAttributeMaxDynamicSharedMemorySize, GEMM_SMEM);
        cudaFuncSetAttribute(attn_kernel, cudaFuncAttributeMaxDynamicSharedMemorySize, ATTN_SMEM);
        cudaFuncSetAttribute(proj_gemm, cudaFuncAttributeMaxDynamicSharedMemorySize, GEMM_SMEM);
    }

    prep<<<XB + WBLK, 256>>>(x, Wq, Wk, Wv, Wp);
    cudaEventRecord(evPrep, 0);
    cudaStreamWaitEvent(sA, evPrep, 0);
    cudaStreamWaitEvent(sB, evPrep, 0);

    // chain A (batches 21..42 = 22 batches, rows 5376..11007) on stream A
    qkv_gemm<<<dim3(44, 9), 256, GEMM_SMEM, sA>>>(5376);
    attn_kernel<<<dim3(NH, 22), 256, ATTN_SMEM, sA>>>(21);
    proj_gemm<<<dim3(44, 3), 256, GEMM_SMEM, sA>>>(5376, bp, out);

    // chain B (batches 43..63 = 21 batches, rows 11008..16383) on stream B
    qkv_gemm<<<dim3(42, 9), 256, GEMM_SMEM, sB>>>(11008);
    attn_kernel<<<dim3(NH, 21), 256, ATTN_SMEM, sB>>>(43);
    proj_gemm<<<dim3(42, 3), 256, GEMM_SMEM, sB>>>(11008, bp, out);

    // chain 0 (batches 0..20 = 21 batches, rows 0..5375) on the origin stream
    qkv_gemm<<<dim3(42, 9), 256, GEMM_SMEM>>>(0);
    attn_kernel<<<dim3(NH, 21), 256, ATTN_SMEM>>>(0);
    proj_gemm<<<dim3(42, 3), 256, GEMM_SMEM>>>(0, bp, out);

    cudaEventRecord(evA, sA);
    cudaEventRecord(evB, sB);
    cudaStreamWaitEvent(0, evA, 0);
    cudaStreamWaitEvent(0, evB, 0);
}

// round 17
// speedup vs baseline: 1.0641x; 1.0641x over previous
#include <cuda_runtime.h>
#include <cuda_fp16.h>
#include <cstdint>

#define NB 64
#define NT 256
#define NC 384
#define NH 6
#define ND 64
#define BTOK (NB*NT)                 // 16384 tokens
#define BHTD ((size_t)NB*NH*NT*ND)   // 6,291,456 elements per q/k/v
#define NQKV 1152                    // 3*384 output cols of merged qkv

// ---------------- scratch (no allocations allowed) ----------------
__device__ __half g_qkvh[3 * BHTD];                // q(pre-scaled),k,v [z][B,H,T,D]
__device__ __half g_aoh[(size_t)BTOK * NC];        // attn out [B,T,H*D]
__device__ __half g_xh[(size_t)BTOK * NC];         // x in fp16 [M][K]
__device__ __half g_wth[(size_t)NQKV * NC];        // qkv weights [n][k] K-major
__device__ __half g_wpth[(size_t)NC * NC];         // Wp transposed [n][k]

// ---------------- helpers ----------------
__device__ __forceinline__ void mma16(float d[4], const uint32_t a[4], const uint32_t b[2]) {
    asm volatile(
        "mma.sync.aligned.m16n8k16.row.col.f32.f16.f16.f32 "
        "{%0,%1,%2,%3}, {%4,%5,%6,%7}, {%8,%9}, {%0,%1,%2,%3};"
        : "+f"(d[0]), "+f"(d[1]), "+f"(d[2]), "+f"(d[3])
        : "r"(a[0]), "r"(a[1]), "r"(a[2]), "r"(a[3]), "r"(b[0]), "r"(b[1]));
}

__device__ __forceinline__ void ldsm_x4(uint32_t r[4], uint32_t addr) {
    asm volatile("ldmatrix.sync.aligned.m8n8.x4.shared.b16 {%0,%1,%2,%3}, [%4];"
        : "=r"(r[0]), "=r"(r[1]), "=r"(r[2]), "=r"(r[3]) : "r"(addr));
}

__device__ __forceinline__ uint32_t packh2(float lo, float hi) {
    __half2 h = __floats2half2_rn(lo, hi);
    return *reinterpret_cast<uint32_t*>(&h);
}

__device__ __forceinline__ void cpa16(uint32_t dst, const void* src) {
    asm volatile("cp.async.cg.shared.global [%0], [%1], 16;" :: "r"(dst), "l"(src));
}
__device__ __forceinline__ void cpa_commit() { asm volatile("cp.async.commit_group;"); }
__device__ __forceinline__ void cpa_wait1()  { asm volatile("cp.async.wait_group 1;"); }
__device__ __forceinline__ void cpa_wait0()  { asm volatile("cp.async.wait_group 0;"); }

// ---------------------------------------------------------------------------
// Kernel 0a: weight prep — transpose + fp16. grid (2304), 256 threads.
// Kernel 0b: x prep (half) — fp16 convert rows. grid (1536), 256 threads.
// ---------------------------------------------------------------------------
#define WQKV (NQKV * NC)              // 442368
#define WBLK ((WQKV + NC * NC + 255) / 256)   // 2304
#define XHBLK 1536                     // (16384/2)*384/8/256

__global__ __launch_bounds__(256) void prep_w(
    const float* __restrict__ Wq, const float* __restrict__ Wk,
    const float* __restrict__ Wv, const float* __restrict__ Wp)
{
    int e = blockIdx.x * 256 + threadIdx.x;
    if (e < WQKV) {
        int n = e / NC, k = e % NC;
        int z = n / NC, rn = n % NC, hh = rn >> 6, d = rn & 63;
        const float* W = (z == 0 ? Wq : (z == 1 ? Wk : Wv));
        g_wth[e] = __float2half_rn(W[(hh * NC + k) * ND + d]);
    } else {
        int e2 = e - WQKV;
        int n = e2 / NC, k = e2 % NC;
        g_wpth[e2] = __float2half_rn(Wp[k * NC + n]);
    }
}

__global__ __launch_bounds__(256) void prep_x(int blkbase, const float* __restrict__ x)
{
    size_t i = ((size_t)(blkbase + blockIdx.x) * 256 + threadIdx.x) * 8;
    float4 v0 = *(const float4*)(x + i);
    float4 v1 = *(const float4*)(x + i + 4);
    uint4 p;
    p.x = packh2(v0.x, v0.y); p.y = packh2(v0.z, v0.w);
    p.z = packh2(v1.x, v1.y); p.w = packh2(v1.z, v1.w);
    *(uint4*)(g_xh + i) = p;
}

// ---------------------------------------------------------------------------
// fp16 pipelined GEMM core: CTA 128x128, 8 warps (2x4), warp tile 64x32,
// k-chunk 64, 3-stage cp.async. Pitch 36 words = 144 B rows.
// ---------------------------------------------------------------------------
#define GP 36                         // words per row (32 used = k-chunk 64)
#define ASW (128 * GP)                // 4608 words
#define STGW (2 * ASW)                // 9216 words per stage (A + B)
#define GEMM_SMEM (3 * STGW * 4)      // 110,592 B
#define KITERS 6                      // 384 / 64

__device__ __forceinline__ void gm_issue(
    uint32_t sbase, const __half* __restrict__ A, const __half* __restrict__ B,
    int m0, int n0, int k0w, int tid)
{
    uint32_t as = sbase, bs = sbase + ASW * 4;
#pragma unroll
    for (int i = 0; i < 4; i++) {
        int e = tid + i * 256;                 // 0..1023
        int r = e >> 3, q = (e & 7) * 4;       // r: row, q: word-in-row
        cpa16(as + (r * GP + q) * 4, (const char*)(A + (size_t)(m0 + r) * NC) + (k0w + q) * 4);
    }
#pragma unroll
    for (int i = 0; i < 4; i++) {
        int e = tid + i * 256;
        int r = e >> 3, q = (e & 7) * 4;
        cpa16(bs + (r * GP + q) * 4, (const char*)(B + (size_t)(n0 + r) * NC) + (k0w + q) * 4);
    }
}

// one k64 step (4 k16 sub-steps); warp tile 64x32; fragments via ldmatrix
__device__ __forceinline__ void gm_step(
    uint32_t asb, uint32_t bsb, int wm, int wn, int lane, float acc[4][4][4])
{
    const int arow = wm + (lane & 15);                    // + mt*16
    const int acol = (lane >> 4) * 4;                     // 0 | 4
    const int brow = wn + (lane & 7) + ((lane & 16) >> 1);// + nt2*16
    const int bcol = (lane & 8) >> 1;                     // 0 | 4
#pragma unroll
    for (int ks = 0; ks < 4; ks++) {
        const int kb = ks * 8;
        uint32_t af[4][4], bf[4][2];
#pragma unroll
        for (int mt = 0; mt < 4; mt++)
            ldsm_x4(af[mt], asb + (((arow + mt * 16) * GP) + kb + acol) * 4);
#pragma unroll
        for (int nt2 = 0; nt2 < 2; nt2++) {
            uint32_t t[4];
            ldsm_x4(t, bsb + (((brow + nt2 * 16) * GP) + kb + bcol) * 4);
            bf[2 * nt2][0] = t[0]; bf[2 * nt2][1] = t[1];
            bf[2 * nt2 + 1][0] = t[2]; bf[2 * nt2 + 1][1] = t[3];
        }
#pragma unroll
        for (int mt = 0; mt < 4; mt++)
#pragma unroll
            for (int nt = 0; nt < 4; nt++)
                mma16(acc[mt][nt], af[mt], bf[nt]);
    }
}

// ---------------------------------------------------------------------------
// Kernel 1: merged QKV GEMM (batch-half). grid (64, 9), 256 threads.
// ---------------------------------------------------------------------------
__global__ __launch_bounds__(256, 2) void qkv_gemm(int mbase)
{
    extern __shared__ uint32_t sh[];
    const int tid = threadIdx.x, lane = tid & 31, warp = tid >> 5;
    const int gid = lane >> 2, tig = lane & 3;
    const int m0 = mbase + blockIdx.x * 128;
    const int n0 = blockIdx.y * 128;
    const int z = n0 / NC, nb = n0 % NC;
    const int wm = (warp >> 2) * 64, wn = (warp & 3) * 32;
    const uint32_t sb = (uint32_t)__cvta_generic_to_shared(sh);

    float acc[4][4][4];
#pragma unroll
    for (int mt = 0; mt < 4; mt++)
#pragma unroll
        for (int nt = 0; nt < 4; nt++)
#pragma unroll
            for (int q = 0; q < 4; q++) acc[mt][nt][q] = 0.f;

    gm_issue(sb, g_xh, g_wth, m0, n0, 0, tid);  cpa_commit();
    gm_issue(sb + STGW * 4, g_xh, g_wth, m0, n0, 32, tid);  cpa_commit();

    for (int it = 0; it < KITERS; it++) {
        cpa_wait1();
        __syncthreads();
        if (it + 2 < KITERS)
            gm_issue(sb + ((it + 2) % 3) * STGW * 4, g_xh, g_wth, m0, n0, (it + 2) * 32, tid);
        cpa_commit();
        uint32_t buf = sb + (it % 3) * STGW * 4;
        gm_step(buf, buf + ASW * 4, wm, wn, lane, acc);
    }

    const float scale = (z == 0) ? 0.125f : 1.0f;
#pragma unroll
    for (int mt = 0; mt < 4; mt++) {
        int m = m0 + wm + mt * 16 + gid;
        int b1 = m >> 8, t1 = m & 255;
        int b2 = (m + 8) >> 8, t2 = (m + 8) & 255;
#pragma unroll
        for (int nt = 0; nt < 4; nt++) {
            int c = wn + nt * 8 + 2 * tig;
            int nl = nb + c, h = nl >> 6, d = nl & 63;
            __half* p0 = g_qkvh + z * BHTD + (((size_t)b1 * NH + h) * NT + t1) * ND + d;
            __half* p1 = g_qkvh + z * BHTD + (((size_t)b2 * NH + h) * NT + t2) * ND + d;
            *(uint32_t*)p0 = packh2(acc[mt][nt][0] * scale, acc[mt][nt][1] * scale);
            *(uint32_t*)p1 = packh2(acc[mt][nt][2] * scale, acc[mt][nt][3] * scale);
        }
    }
}

// ---------------------------------------------------------------------------
// Kernel 2: causal flash attention per (b,h), batch-half via bbase.
// grid (6, 32), 256 threads. Balanced warp pairing (5 tiles/warp).
// ---------------------------------------------------------------------------
#define KSW 36    // Ks pitch (words): 144 B rows, conflict-free ldsm
#define VSW 132   // Vs pitch (words): 528 B rows, 16B-aligned
#define ATTN_SMEM ((256 * KSW + 64 * VSW) * 4)   // 70,656 B

__global__ __launch_bounds__(256, 2) void attn_kernel(int bbase)
{
    extern __shared__ uint32_t sh[];
    uint32_t* Ks = sh;                  // [s=256][d-pair, 32 used]
    uint32_t* Vs = sh + 256 * KSW;      // [d=64][s-pair, 128 used]

    const int tid = threadIdx.x, lane = tid & 31, warp = tid >> 5;
    const int gid = lane >> 2, tig = lane & 3;
    const int h = blockIdx.x, b = bbase + blockIdx.y;

    const __half* qbh = g_qkvh + ((size_t)(b * NH + h) * NT) * ND;
    const __half* kbh = qbh + BHTD;
    const __half* vbh = qbh + 2 * BHTD;

    uint32_t ksb = (uint32_t)__cvta_generic_to_shared(Ks);
    uint32_t vsb = (uint32_t)__cvta_generic_to_shared(Vs);
#pragma unroll
    for (int i = 0; i < 8; i++) {
        int e = tid + i * 256;
        int s = e >> 3, q = (e & 7) * 4;
        cpa16(ksb + (s * KSW + q) * 4, (const char*)(kbh + (size_t)s * ND) + q * 4);
    }
    cpa_commit();

    // V transpose to [d][s-pair]; banks (4d+sp) mod 32 all distinct
#pragma unroll
    for (int i = 0; i < 32; i++) {
        int e = tid + i * 256;
        int d  = ((e >> 5) & 7) * 8 + (e & 7);
        int sp = (e >> 8) * 4 + ((e >> 3) & 3);
        uint32_t lo = __half_as_ushort(vbh[(size_t)(2 * sp) * ND + d]);
        uint32_t hi = __half_as_ushort(vbh[(size_t)(2 * sp + 1) * ND + d]);
        Vs[d * VSW + sp] = lo | (hi << 16);
    }
    cpa_wait0();
    __syncthreads();

    const uint32_t* qw = (const uint32_t*)qbh;   // [t][32 words]
    const int lrow = (lane & 7) + ((lane & 16) >> 1);
    const int lcol = (lane & 8) >> 1;

    for (int pass = 0; pass < 2; pass++) {
        const int grp = (pass == 0) ? warp : (15 - warp);   // 16-row group, 0..15
        const int qr0 = grp * 16 + gid;                     // global q row
        uint32_t qf[4][4];
#pragma unroll
        for (int kk = 0; kk < 4; kk++) {
            qf[kk][0] = qw[qr0 * 32 + kk * 8 + tig];
            qf[kk][1] = qw[(qr0 + 8) * 32 + kk * 8 + tig];
            qf[kk][2] = qw[qr0 * 32 + kk * 8 + tig + 4];
            qf[kk][3] = qw[(qr0 + 8) * 32 + kk * 8 + tig + 4];
        }

        float oacc[8][4];
#pragma unroll
        for (int nt = 0; nt < 8; nt++)
#pragma unroll
            for (int q = 0; q < 4; q++) oacc[nt][q] = 0.f;
        float l0 = 0.f, l1 = 0.f;

        const int jmax = (grp * 16 + 15) >> 6;
        for (int j = 0; j <= jmax; j++) {
            float sacc[8][4];
#pragma unroll
            for (int nt = 0; nt < 8; nt++)
#pragma unroll
                for (int q = 0; q < 4; q++) sacc[nt][q] = 0.f;

#pragma unroll
            for (int kk = 0; kk < 4; kk++)
#pragma unroll
                for (int nt2 = 0; nt2 < 4; nt2++) {
                    uint32_t t[4];
                    int srow = j * 64 + nt2 * 16 + lrow;
                    ldsm_x4(t, ksb + ((srow * KSW) + kk * 8 + lcol) * 4);
                    mma16(sacc[2 * nt2], qf[kk], t);
                    mma16(sacc[2 * nt2 + 1], qf[kk], t + 2);
                }

            // causal mask (only when this key tile can overlap the diagonal)
            const int qg0 = qr0, qg1 = qr0 + 8;
            if (j * 64 + 63 > grp * 16) {
#pragma unroll
                for (int nt = 0; nt < 8; nt++) {
                    int kg = j * 64 + nt * 8 + 2 * tig;
                    if (kg > qg0) sacc[nt][0] = -1e30f;
                    if (kg + 1 > qg0) sacc[nt][1] = -1e30f;
                    if (kg > qg1) sacc[nt][2] = -1e30f;
                    if (kg + 1 > qg1) sacc[nt][3] = -1e30f;
                }
            }

            // direct softmax: exp + row-sum
            float rs0 = 0.f, rs1 = 0.f;
#pragma unroll
            for (int nt = 0; nt < 8; nt++) {
                sacc[nt][0] = __expf(fminf(sacc[nt][0], 25.f));
                sacc[nt][1] = __expf(fminf(sacc[nt][1], 25.f));
                sacc[nt][2] = __expf(fminf(sacc[nt][2], 25.f));
                sacc[nt][3] = __expf(fminf(sacc[nt][3], 25.f));
                rs0 += sacc[nt][0] + sacc[nt][1];
                rs1 += sacc[nt][2] + sacc[nt][3];
            }
            rs0 += __shfl_xor_sync(0xffffffffu, rs0, 1);
            rs0 += __shfl_xor_sync(0xffffffffu, rs0, 2);
            rs1 += __shfl_xor_sync(0xffffffffu, rs1, 1);
            rs1 += __shfl_xor_sync(0xffffffffu, rs1, 2);
            l0 += rs0;
            l1 += rs1;

            // P -> fp16 A-fragments in registers
            uint32_t pp[4][4];
#pragma unroll
            for (int kw = 0; kw < 4; kw++) {
                pp[kw][0] = packh2(sacc[2 * kw][0],     sacc[2 * kw][1]);
                pp[kw][1] = packh2(sacc[2 * kw][2],     sacc[2 * kw][3]);
                pp[kw][2] = packh2(sacc[2 * kw + 1][0], sacc[2 * kw + 1][1]);
                pp[kw][3] = packh2(sacc[2 * kw + 1][2], sacc[2 * kw + 1][3]);
            }

            // O += P * V
#pragma unroll
            for (int kw = 0; kw < 4; kw++)
#pragma unroll
                for (int dt2 = 0; dt2 < 4; dt2++) {
                    uint32_t t[4];
                    int drow = dt2 * 16 + lrow;
                    ldsm_x4(t, vsb + ((drow * VSW) + j * 32 + kw * 8 + lcol) * 4);
                    mma16(oacc[2 * dt2], pp[kw], t);
                    mma16(oacc[2 * dt2 + 1], pp[kw], t + 2);
                }
        }

        // epilogue -> g_aoh [B,T,H*D] half (rows grp*16 .. grp*16+15)
        const float inv0 = 1.f / l0, inv1 = 1.f / l1;
        __half* op = g_aoh + ((size_t)(b * NT) + grp * 16) * NC + h * ND;
        const int r0 = gid;
#pragma unroll
        for (int nt = 0; nt < 8; nt++) {
            int cc = nt * 8 + 2 * tig;
            *(uint32_t*)(op + (size_t)r0 * NC + cc) =
                packh2(oacc[nt][0] * inv0, oacc[nt][1] * inv0);
            *(uint32_t*)(op + (size_t)(r0 + 8) * NC + cc) =
                packh2(oacc[nt][2] * inv1, oacc[nt][3] * inv1);
        }
    }
}

// ---------------------------------------------------------------------------
// Kernel 3: output projection + bias (batch-half). grid (64, 3), 256 threads.
// ---------------------------------------------------------------------------
__global__ __launch_bounds__(256, 2) void proj_gemm(
    int mbase, const float* __restrict__ bp, float* __restrict__ out)
{
    extern __shared__ uint32_t sh[];
    const int tid = threadIdx.x, lane = tid & 31, warp = tid >> 5;
    const int gid = lane >> 2, tig = lane & 3;
    const int m0 = mbase + blockIdx.x * 128;
    const int n0 = blockIdx.y * 128;
    const int wm = (warp >> 2) * 64, wn = (warp & 3) * 32;
    const uint32_t sb = (uint32_t)__cvta_generic_to_shared(sh);

    float acc[4][4][4];
#pragma unroll
    for (int mt = 0; mt < 4; mt++)
#pragma unroll
        for (int nt = 0; nt < 4; nt++)
#pragma unroll
            for (int q = 0; q < 4; q++) acc[mt][nt][q] = 0.f;

    gm_issue(sb, g_aoh, g_wpth, m0, n0, 0, tid);  cpa_commit();
    gm_issue(sb + STGW * 4, g_aoh, g_wpth, m0, n0, 32, tid);  cpa_commit();

    for (int it = 0; it < KITERS; it++) {
        cpa_wait1();
        __syncthreads();
        if (it + 2 < KITERS)
            gm_issue(sb + ((it + 2) % 3) * STGW * 4, g_aoh, g_wpth, m0, n0, (it + 2) * 32, tid);
        cpa_commit();
        uint32_t buf = sb + (it % 3) * STGW * 4;
        gm_step(buf, buf + ASW * 4, wm, wn, lane, acc);
    }

#pragma unroll
    for (int mt = 0; mt < 4; mt++) {
        int r = wm + mt * 16 + gid;
#pragma unroll
        for (int nt = 0; nt < 4; nt++) {
            int c = n0 + wn + nt * 8 + 2 * tig;
            float b0 = bp[c], b1 = bp[c + 1];
            *(float2*)(out + (size_t)(m0 + r) * NC + c) =
                make_float2(acc[mt][nt][0] + b0, acc[mt][nt][1] + b1);
            *(float2*)(out + (size_t)(m0 + r + 8) * NC + c) =
                make_float2(acc[mt][nt][2] + b0, acc[mt][nt][3] + b1);
        }
    }
}

// ---------------------------------------------------------------------------
// Launch: two-half pipeline on 2 forked streams (R14's proven-safe resource
// set) + overlapped prep: prep_w on origin, prep_x halves on the workers.
// Streams/events created once on the first call.
// ---------------------------------------------------------------------------
extern "C" void kernel_launch(void* const* d_in, const int* in_sizes, int n_in,
                              void* d_out, int out_size)
{
    const float* x  = (const float*)d_in[0];
    const float* Wq = (const float*)d_in[1];
    const float* Wk = (const float*)d_in[2];
    const float* Wv = (const float*)d_in[3];
    const float* Wp = (const float*)d_in[4];
    const float* bp = (const float*)d_in[5];
    float* out = (float*)d_out;

    static cudaStream_t sA = nullptr, sB = nullptr;
    static cudaEvent_t evW = nullptr, evA = nullptr, evB = nullptr;
    if (sA == nullptr) {
        int prioLo = 0, prioHi = 0;
        cudaDeviceGetStreamPriorityRange(&prioLo, &prioHi);
        cudaStreamCreateWithPriority(&sA, cudaStreamNonBlocking, prioHi);
        cudaStreamCreateWithPriority(&sB, cudaStreamNonBlocking, prioLo);
        cudaEventCreateWithFlags(&evW, cudaEventDisableTiming);
        cudaEventCreateWithFlags(&evA, cudaEventDisableTiming);
        cudaEventCreateWithFlags(&evB, cudaEventDisableTiming);

        cudaFuncSetAttribute(qkv_gemm, cudaFuncAttributeMaxDynamicSharedMemorySize, GEMM_SMEM);
        cudaFuncSetAttribute(attn_kernel, cudaFuncAttributeMaxDynamicSharedMemorySize, ATTN_SMEM);
        cudaFuncSetAttribute(proj_gemm, cudaFuncAttributeMaxDynamicSharedMemorySize, GEMM_SMEM);
    }

    // weight prep on origin; x halves on the worker streams (independent of W)
    prep_w<<<WBLK, 256>>>(Wq, Wk, Wv, Wp);
    cudaEventRecord(evW, 0);

    prep_x<<<XHBLK, 256, 0, sA>>>(0, x);
    prep_x<<<XHBLK, 256, 0, sB>>>(XHBLK, x);

    cudaStreamWaitEvent(sA, evW, 0);
    cudaStreamWaitEvent(sB, evW, 0);

    // half 0 (rows 0..8191, batches 0..31) on high-priority stream A
    qkv_gemm<<<dim3(64, 9), 256, GEMM_SMEM, sA>>>(0);
    attn_kernel<<<dim3(NH, 32), 256, ATTN_SMEM, sA>>>(0);
    proj_gemm<<<dim3(64, 3), 256, GEMM_SMEM, sA>>>(0, bp, out);

    // half 1 (rows 8192..16383, batches 32..63) on stream B
    qkv_gemm<<<dim3(64, 9), 256, GEMM_SMEM, sB>>>(8192);
    attn_kernel<<<dim3(NH, 32), 256, ATTN_SMEM, sB>>>(32);
    proj_gemm<<<dim3(64, 3), 256, GEMM_SMEM, sB>>>(8192, bp, out);

    cudaEventRecord(evA, sA);
    cudaEventRecord(evB, sB);
    cudaStreamWaitEvent(0, evA, 0);
    cudaStreamWaitEvent(0, evB, 0);
}